// round 17
// baseline (speedup 1.0000x reference)
#include <cuda_runtime.h>
#include <cuda_fp16.h>
#include <cstdint>

// ---------------------------------------------------------------------------
// LMMD loss, GB300.  Gram matrix via mma.sync.m16n8k16 fp16 (fp32 accum),
// 3-stage cp.async pipeline.  Epilogue fully packed f32x2 (2 elems/op).
// Diagonal tiles use the symmetry identity sum_{p<=q} f*wK == sum_all wK,
// so no per-element f anywhere.  TT weights on tensor cores.  3 launches.
// ---------------------------------------------------------------------------

#define TPD 32
#define NT  64
#define TS  128
#define KC  32
#define NCHUNK 8
#define NTILES 2080
#define TVSC  512.0f
#define TVSC_INV2 (1.0f/(512.0f*512.0f))

__device__ __align__(16) __half g_xh[8192*256];
__device__ __align__(16) __half g_tvh[4096*32];
__device__ float g_sq[8192];
__device__ float g_sw[4096];
__device__ int   g_cls[4096];
__device__ float g_tv[4096*32];
__device__ float g_colsum[256];
__device__ float g_blk_s[16*31], g_blk_t[16*31], g_blk_a[16*31];
__device__ float g_swc[32], g_tvd[32];
__device__ float g_scalars[4];      // [0]=neg_r, [1]=1/n_idx
__device__ int   g_use64;
__device__ int   g_ctr0, g_ctr1, g_ctr2;   // self-resetting (graph replay safe)
__device__ float g_partials[NTILES];

static __device__ __forceinline__ uint32_t smem_u32(const void* p) {
  uint32_t a;
  asm("{ .reg .u64 t; cvta.to.shared.u64 t, %1; cvt.u32.u64 %0, t; }"
      : "=r"(a) : "l"(p));
  return a;
}

// ---- packed f32x2 helpers -------------------------------------------------
static __device__ __forceinline__ unsigned long long pk2(float lo, float hi) {
  unsigned long long d;
  asm("mov.b64 %0, {%1, %2};" : "=l"(d)
      : "r"(__float_as_uint(lo)), "r"(__float_as_uint(hi)));
  return d;
}
static __device__ __forceinline__ unsigned long long add2_(unsigned long long a, unsigned long long b) {
  unsigned long long d;
  asm("add.rn.f32x2 %0, %1, %2;" : "=l"(d) : "l"(a), "l"(b));
  return d;
}
static __device__ __forceinline__ unsigned long long mul2_(unsigned long long a, unsigned long long b) {
  unsigned long long d;
  asm("mul.rn.f32x2 %0, %1, %2;" : "=l"(d) : "l"(a), "l"(b));
  return d;
}
static __device__ __forceinline__ unsigned long long fma2_(unsigned long long a, unsigned long long b, unsigned long long c) {
  unsigned long long d;
  asm("fma.rn.f32x2 %0, %1, %2, %3;" : "=l"(d) : "l"(a), "l"(b), "l"(c));
  return d;
}

// ---------------------------------------------------------------------------
// Launch 0: blocks 0..2047 fp16 convert; 2048..2063 label stats (16 blocks,
// per-block width detect + partials; last derives weights); 2064 colsum zero.
// ---------------------------------------------------------------------------
__global__ void k_pre(const float* __restrict__ s, const float* __restrict__ t,
                      const void* __restrict__ slab,
                      const float* __restrict__ t_label) {
  int b = blockIdx.x, tt = threadIdx.x;
  if (b < 2048) {
    long base = ((long)b * 256 + tt) * 4;
    const float* inp = (base < 1048576) ? (s + base) : (t + (base - 1048576));
    float4 v = *(const float4*)inp;
    uint32_t h01, h23;
    asm("cvt.rn.f16x2.f32 %0, %1, %2;" : "=r"(h01) : "f"(v.y), "f"(v.x));
    asm("cvt.rn.f16x2.f32 %0, %1, %2;" : "=r"(h23) : "f"(v.w), "f"(v.z));
    uint2 w = make_uint2(h01, h23);
    *(uint2*)&g_xh[base] = w;
    return;
  }
  if (b == 2064) { g_colsum[tt] = 0.f; return; }
  int bb = b - 2048;                 // 0..15
  const int* l32 = (const int*)slab;
  const long long* l64 = (const long long*)slab;
  __shared__ float sh_s[31], sh_t[31], sh_a[31];
  __shared__ int nzf, isLast;
  int lane = tt & 31;
  if (tt < 31) { sh_s[tt] = 0.f; sh_t[tt] = 0.f; sh_a[tt] = 0.f; }
  if (tt == 0) nzf = 0;
  __syncthreads();
  // label-width detect on rows < 2048 only (safe if buffer is int32-sized)
  int drow = (bb & 7) * 256 + tt;
  if (l32[2*drow + 1] != 0) atomicOr(&nzf, 1);
  __syncthreads();
  bool u64 = (nzf == 0);
  if (tt == 0 && bb == 0) g_use64 = u64 ? 1 : 0;
  int row = bb * 256 + tt;
  int c = u64 ? (int)l64[row] : l32[row];
  atomicAdd(&sh_s[c], 1.f);
  const float* r = t_label + row * 31;
  float m = r[0]; int am = 0;
  #pragma unroll
  for (int cc = 0; cc < 31; cc++) {
    float v = r[cc];
    if (v > m) { m = v; am = cc; }
    float ss = v;
    #pragma unroll
    for (int o = 16; o > 0; o >>= 1) ss += __shfl_down_sync(0xffffffffu, ss, o);
    if (lane == 0) atomicAdd(&sh_t[cc], ss);
  }
  atomicAdd(&sh_a[am], 1.f);
  __syncthreads();
  if (tt < 31) {
    g_blk_s[bb*31+tt] = sh_s[tt];
    g_blk_t[bb*31+tt] = sh_t[tt];
    g_blk_a[bb*31+tt] = sh_a[tt];
  }
  __syncthreads();
  if (tt == 0) { __threadfence(); isLast = (atomicAdd(&g_ctr0, 1) == 15); }
  __syncthreads();
  if (!isLast) return;
  if (tt == 0) g_ctr0 = 0;
  __threadfence();
  float msk = 0.f;
  if (tt < 31) {
    float scnt = 0.f, tcnt = 0.f, acnt = 0.f;
    for (int k = 0; k < 16; k++) {
      scnt += g_blk_s[k*31+tt]; tcnt += g_blk_t[k*31+tt]; acnt += g_blk_a[k*31+tt];
    }
    msk = (scnt > 0.f && acnt > 0.f) ? 1.f : 0.f;
    g_swc[tt] = msk / ((scnt == 0.f) ? 100.f : scnt);
    g_tvd[tt] = msk / ((tcnt == 0.f) ? 100.f : tcnt);
  }
  if (tt == 31) { g_swc[31] = 0.f; g_tvd[31] = 0.f; }
  if (tt < 32) {
    float n = msk;
    #pragma unroll
    for (int o = 16; o > 0; o >>= 1) n += __shfl_down_sync(0xffffffffu, n, o);
    if (tt == 0) g_scalars[1] = 1.f / fmaxf(n, 1.f);
  }
}

// ---------------------------------------------------------------------------
// Launch 1: blocks 0..255 = sq norms + colsums (+bw in last norm block);
//           blocks 256..383 = per-row weight / tv / tvh fill.
// ---------------------------------------------------------------------------
__global__ void k_fillnorm(const float* __restrict__ src,
                           const float* __restrict__ tgt,
                           const void* __restrict__ slab,
                           const float* __restrict__ t_label) {
  __shared__ double sd[256];
  __shared__ int isLast;
  int b = blockIdx.x, t = threadIdx.x;
  if (b >= 256) {
    int bb = b - 256;
    bool u64 = (g_use64 != 0);
    int stride = 128 * 256;
    for (int i = bb * 256 + t; i < 4096; i += stride) {
      int c = u64 ? (int)((const long long*)slab)[i] : ((const int*)slab)[i];
      g_cls[i] = c;
      g_sw[i]  = g_swc[c];
    }
    for (int idx = bb * 256 + t; idx < 4096*32; idx += stride) {
      int i = idx >> 5, c = idx & 31;
      float v = (c < 31) ? t_label[i*31 + c] * g_tvd[c] : 0.f;
      g_tv[idx]  = v;
      g_tvh[idx] = __float2half(v * TVSC);
    }
    return;
  }
  int warp = t >> 5, lane = t & 31;
  #pragma unroll
  for (int it = 0; it < 4; it++) {
    int row = b * 32 + it * 8 + warp;
    const float* r = (row < 4096) ? src + row*256 : tgt + (row - 4096)*256;
    float s = 0.f;
    #pragma unroll
    for (int k = 0; k < 8; k++) { float v = r[lane + 32*k]; s = fmaf(v, v, s); }
    #pragma unroll
    for (int o = 16; o > 0; o >>= 1) s += __shfl_down_sync(0xffffffffu, s, o);
    if (lane == 0) g_sq[row] = s;
  }
  float cs = 0.f;
  for (int rr = 0; rr < 32; rr++) {
    int row = b * 32 + rr;
    const float* r = (row < 4096) ? src + row*256 : tgt + (row - 4096)*256;
    cs += r[t];
  }
  atomicAdd(&g_colsum[t], cs);
  if (t == 0) {
    __threadfence();
    isLast = (atomicAdd(&g_ctr1, 1) == 255);
  }
  __syncthreads();
  if (!isLast) return;
  if (t == 0) g_ctr1 = 0;
  __threadfence();
  double s = 0.0;
  for (int i = t; i < 8192; i += 256) s += (double)g_sq[i];
  sd[t] = s; __syncthreads();
  for (int o = 128; o > 0; o >>= 1) { if (t < o) sd[t] += sd[t + o]; __syncthreads(); }
  double S1 = sd[0];
  __syncthreads();
  double c = (double)g_colsum[t];
  sd[t] = c * c; __syncthreads();
  for (int o = 128; o > 0; o >>= 1) { if (t < o) sd[t] += sd[t + o]; __syncthreads(); }
  if (t == 0) {
    double n = 8192.0;
    double suml2 = 2.0*n*S1 - 2.0*sd[0];
    double bw = suml2 / (n*n - n);
    bw = fmax(bw, 1e-6) / 4.0;
    g_scalars[0] = (float)(-1.4426950408889634 / (16.0 * bw));
  }
}

// ---------------------------------------------------------------------------
// Launch 2: main tile kernel + final reduction (last CTA).
// ---------------------------------------------------------------------------
union SmemU {
  __half mm[3][2][4096];    // 48KB stage buffers
  struct {
    float tv0[4224], tv1[4224];
    float sqP[TS], sqQ[TS], swP[TS], swQ[TS];
    float red[32];
    int   cP[TS], cQ[TS];
    double sdred[256];
  } ep;
};

#define LDMX4(r0,r1,r2,r3,addr)                                                \
  asm volatile("ldmatrix.sync.aligned.m8n8.x4.shared.b16 {%0,%1,%2,%3}, [%4];" \
    : "=r"(r0), "=r"(r1), "=r"(r2), "=r"(r3) : "r"(addr))

#define MMA_F16(c, a, b)                                                       \
  asm volatile("mma.sync.aligned.m16n8k16.row.col.f32.f16.f16.f32 "            \
    "{%0,%1,%2,%3}, {%4,%5,%6,%7}, {%8,%9}, {%0,%1,%2,%3};"                    \
    : "+f"((c)[0]), "+f"((c)[1]), "+f"((c)[2]), "+f"((c)[3])                   \
    : "r"((a)[0]), "r"((a)[1]), "r"((a)[2]), "r"((a)[3]),                      \
      "r"((b)[0]), "r"((b)[1]))

static __device__ __forceinline__ void issue_chunk(
    const __half* __restrict__ pBase, const __half* __restrict__ qBase,
    uint32_t aDst, uint32_t bDst, int kb, int tid) {
  #pragma unroll
  for (int it = 0; it < 2; it++) {
    int gi  = tid * 2 + it;
    int row = gi >> 2, g = gi & 3;
    const __half* sA = pBase + row*256 + kb*KC + g*8;
    const __half* sB = qBase + row*256 + kb*KC + g*8;
    uint32_t off = (uint32_t)((row >> 3)*512 + g*128 + (row & 7)*16);
    asm volatile("cp.async.cg.shared.global [%0], [%1], 16;"
                 :: "r"(aDst + off), "l"(sA) : "memory");
    asm volatile("cp.async.cg.shared.global [%0], [%1], 16;"
                 :: "r"(bDst + off), "l"(sB) : "memory");
  }
  asm volatile("cp.async.commit_group;" ::: "memory");
}

// packed per-pair kernel contribution (uses enclosing loc2 + constants)
#define PAIRK(w0_, w1_, d0_, d1_, ss2_) do {                                   \
  unsigned long long wf2_ = pk2((w0_), (w1_));                                 \
  unsigned long long d2_  = pk2((d0_), (d1_));                                 \
  unsigned long long l2v_ = fma2_(d2_, NEG2_2, (ss2_));                        \
  unsigned long long x2_  = mul2_(l2v_, NEGR2);                                \
  unsigned long long t2_  = add2_(x2_, MAGIC2);                                \
  unsigned long long u2_  = fma2_(MAGIC2, NEGONE2, t2_);                       \
  unsigned long long r2_  = fma2_(u2_, NEGONE2, x2_);                          \
  unsigned long long p2_  = fma2_(C6_2, r2_, C5_2);                            \
  p2_ = fma2_(p2_, r2_, C4_2);                                                 \
  p2_ = fma2_(p2_, r2_, C3_2);                                                 \
  p2_ = fma2_(p2_, r2_, C2_2);                                                 \
  p2_ = fma2_(p2_, r2_, C1_2);                                                 \
  p2_ = fma2_(p2_, r2_, ONE2);                                                 \
  uint32_t tlo_, thi_, plo_, phi_;                                             \
  asm("mov.b64 {%0, %1}, %2;" : "=r"(tlo_), "=r"(thi_) : "l"(t2_));            \
  asm("mov.b64 {%0, %1}, %2;" : "=r"(plo_), "=r"(phi_) : "l"(p2_));            \
  uint32_t elo_ = plo_ + (tlo_ << 23);                                         \
  uint32_t ehi_ = phi_ + (thi_ << 23);                                         \
  unsigned long long E_;                                                       \
  asm("mov.b64 %0, {%1, %2};" : "=l"(E_) : "r"(elo_), "r"(ehi_));              \
  unsigned long long Eb_ = mul2_(E_, E_);                                      \
  unsigned long long s2_ = add2_(E_, Eb_);                                     \
  unsigned long long Ec_ = mul2_(Eb_, Eb_);                                    \
  unsigned long long Ed_ = mul2_(Ec_, Ec_);                                    \
  s2_ = add2_(s2_, Ec_);                                                       \
  unsigned long long Ee_ = mul2_(Ed_, Ed_);                                    \
  s2_ = add2_(s2_, Ed_);                                                       \
  s2_ = add2_(s2_, Ee_);                                                       \
  loc2 = fma2_(wf2_, s2_, loc2);                                               \
} while (0)

__global__ void __launch_bounds__(256, 2)
k_main(float* __restrict__ out) {
  // reversed triangular decode (heavy TT tiles first): t0 -> (bi <= bj)
  int t0 = (NTILES - 1) - blockIdx.x;
  int bi = (int)(64.5f - sqrtf(4160.25f - 2.f*(float)t0));
  while ((bi+1)*64 - ((bi+1)*bi)/2 <= t0) bi++;
  while (bi*64 - (bi*(bi-1))/2 > t0) bi--;
  int bj = bi + (t0 - (bi*64 - (bi*(bi-1))/2));

  __shared__ __align__(16) SmemU u;
  __shared__ int fin;

  int tid  = threadIdx.x;
  int warp = tid >> 5, lane = tid & 31;
  int warpM = warp & 1, warpN = warp >> 1;

  const __half* pBase = g_xh + (long)bi * TS * 256;
  const __half* qBase = g_xh + (long)bj * TS * 256;

  uint32_t aS[3], bS[3];
  #pragma unroll
  for (int s = 0; s < 3; s++) {
    aS[s] = smem_u32(&u.mm[s][0][0]);
    bS[s] = smem_u32(&u.mm[s][1][0]);
  }

  // precomputed ldmatrix offsets
  int piece = lane >> 3, pr = lane & 7;
  uint32_t offA[2][4], offB[2][2];
  #pragma unroll
  for (int ks = 0; ks < 2; ks++) {
    #pragma unroll
    for (int mi = 0; mi < 4; mi++)
      offA[ks][mi] = (uint32_t)(
          (warpM*8 + mi*2 + (piece & 1))*512 + (2*ks + (piece >> 1))*128 + pr*16);
    #pragma unroll
    for (int np = 0; np < 2; np++) {
      int nt = np*2 + (piece >> 1);
      offB[ks][np] = (uint32_t)(
          (warpN*4 + nt)*512 + (2*ks + (piece & 1))*128 + pr*16);
    }
  }

  float acc[16][4];
  #pragma unroll
  for (int i = 0; i < 16; i++)
    #pragma unroll
    for (int v = 0; v < 4; v++) acc[i][v] = 0.f;

  issue_chunk(pBase, qBase, aS[0], bS[0], 0, tid);
  issue_chunk(pBase, qBase, aS[1], bS[1], 1, tid);

  for (int kb = 0; kb < NCHUNK; kb++) {
    if (kb < NCHUNK-1) asm volatile("cp.async.wait_group 1;" ::: "memory");
    else               asm volatile("cp.async.wait_group 0;" ::: "memory");
    __syncthreads();
    if (kb + 2 < NCHUNK) {
      int s = (kb + 2) % 3;
      issue_chunk(pBase, qBase, aS[s], bS[s], kb + 2, tid);
    }
    uint32_t aB = aS[kb % 3], bB = bS[kb % 3];
    #pragma unroll
    for (int ks = 0; ks < 2; ks++) {
      uint32_t aF[4][4], bF[4][2];
      #pragma unroll
      for (int mi = 0; mi < 4; mi++)
        LDMX4(aF[mi][0], aF[mi][1], aF[mi][2], aF[mi][3], aB + offA[ks][mi]);
      #pragma unroll
      for (int np = 0; np < 2; np++)
        LDMX4(bF[np*2][0], bF[np*2][1], bF[np*2+1][0], bF[np*2+1][1],
              bB + offB[ks][np]);
      #pragma unroll
      for (int mi = 0; mi < 4; mi++)
        #pragma unroll
        for (int ni = 0; ni < 4; ni++)
          MMA_F16(acc[mi*4 + ni], aF[mi], bF[ni]);
    }
    __syncthreads();
  }

  // ---- epilogue metadata ----
  int p0 = bi*TS, q0 = bj*TS;
  bool pS = (bi < TPD), qS = (bj < TPD);
  int type = pS ? (qS ? 0 : 1) : 2;   // 0=SS 1=ST 2=TT
  for (int r = tid; r < TS; r += 256) { u.ep.sqP[r] = g_sq[p0 + r]; u.ep.sqQ[r] = g_sq[q0 + r]; }
  if (type == 0) {
    for (int r = tid; r < TS; r += 256) {
      u.ep.cP[r] = g_cls[p0 + r]; u.ep.swP[r] = g_sw[p0 + r];
      u.ep.cQ[r] = g_cls[q0 + r]; u.ep.swQ[r] = g_sw[q0 + r];
    }
  } else if (type == 1) {
    for (int r = tid; r < TS; r += 256) { u.ep.cP[r] = g_cls[p0 + r]; u.ep.swP[r] = g_sw[p0 + r]; }
    for (int idx = tid; idx < 4096; idx += 256) {
      int r = idx >> 5, c = idx & 31;
      u.ep.tv1[c*132 + r] = g_tv[(q0 - 4096)*32 + idx];
    }
  }
  __syncthreads();

  float neg_r = g_scalars[0];
  bool diag = (bi == bj);

  // per-thread coordinates
  int pv[8]; float sqp[8];
  int qv[8]; float sqq[8];
  #pragma unroll
  for (int pi = 0; pi < 8; pi++) {
    int p = warpM*64 + (pi >> 1)*16 + (pi & 1)*8 + (lane >> 2);
    pv[pi] = p; sqp[pi] = u.ep.sqP[p];
  }
  #pragma unroll
  for (int qi = 0; qi < 8; qi++) {
    int q = warpN*32 + (qi >> 1)*8 + (qi & 1) + 2*(lane & 3);
    qv[qi] = q; sqq[qi] = u.ep.sqQ[q];
  }

  // packed constants (2^r Taylor, ln2 folded)
  const unsigned long long MAGIC2  = pk2(12582912.f, 12582912.f);
  const unsigned long long NEGONE2 = pk2(-1.f, -1.f);
  const unsigned long long ONE2    = pk2(1.f, 1.f);
  const unsigned long long NEG2_2  = pk2(-2.f, -2.f);
  const unsigned long long NEGR2   = pk2(neg_r, neg_r);
  const unsigned long long C1_2 = pk2(0.69314718056f, 0.69314718056f);
  const unsigned long long C2_2 = pk2(0.2402265069f,  0.2402265069f);
  const unsigned long long C3_2 = pk2(0.0555041087f,  0.0555041087f);
  const unsigned long long C4_2 = pk2(0.0096181291f,  0.0096181291f);
  const unsigned long long C5_2 = pk2(0.0013333558f,  0.0013333558f);
  const unsigned long long C6_2 = pk2(1.540353e-4f,   1.540353e-4f);

  unsigned long long sqq2[4];
  #pragma unroll
  for (int ni = 0; ni < 4; ni++) sqq2[ni] = pk2(sqq[ni*2], sqq[ni*2+1]);

  unsigned long long loc2 = 0ULL;   // packed (0, 0)

  if (type == 0) {          // SS
    int cpA[8]; float swpA[8]; int cqA[8]; float swqA[8];
    #pragma unroll
    for (int pi = 0; pi < 8; pi++) { cpA[pi] = u.ep.cP[pv[pi]]; swpA[pi] = u.ep.swP[pv[pi]]; }
    #pragma unroll
    for (int qi = 0; qi < 8; qi++) { cqA[qi] = u.ep.cQ[qv[qi]]; swqA[qi] = u.ep.swQ[qv[qi]]; }
    #pragma unroll
    for (int mi = 0; mi < 4; mi++)
      #pragma unroll
      for (int h = 0; h < 2; h++) {
        int pi = mi*2 + h;
        unsigned long long sqp2 = pk2(sqp[pi], sqp[pi]);
        int cp = cpA[pi]; float swp = swpA[pi];
        #pragma unroll
        for (int ni = 0; ni < 4; ni++) {
          unsigned long long ss2 = add2_(sqp2, sqq2[ni]);
          float w0 = (cp == cqA[ni*2])   ? swp*swqA[ni*2]   : 0.f;
          float w1 = (cp == cqA[ni*2+1]) ? swp*swqA[ni*2+1] : 0.f;
          PAIRK(w0, w1, acc[mi*4+ni][2*h], acc[mi*4+ni][2*h+1], ss2);
        }
      }
  } else if (type == 1) {   // ST (sign folded into ef)
    int cpA[8]; float swpA[8];
    #pragma unroll
    for (int pi = 0; pi < 8; pi++) { cpA[pi] = u.ep.cP[pv[pi]]; swpA[pi] = u.ep.swP[pv[pi]]; }
    #pragma unroll
    for (int mi = 0; mi < 4; mi++)
      #pragma unroll
      for (int h = 0; h < 2; h++) {
        int pi = mi*2 + h;
        unsigned long long sqp2 = pk2(sqp[pi], sqp[pi]);
        int cp = cpA[pi]; float swp = swpA[pi];
        const float* tvrow = &u.ep.tv1[cp*132];
        #pragma unroll
        for (int ni = 0; ni < 4; ni++) {
          unsigned long long ss2 = add2_(sqp2, sqq2[ni]);
          float w0 = swp * tvrow[qv[ni*2]];
          float w1 = swp * tvrow[qv[ni*2+1]];
          PAIRK(w0, w1, acc[mi*4+ni][2*h], acc[mi*4+ni][2*h+1], ss2);
        }
      }
  } else {                  // TT: W on tensor cores (K=32 fp16)
    const __half* tp = g_tvh + (long)(p0 - 4096) * 32;
    const __half* tq = g_tvh + (long)(q0 - 4096) * 32;
    #pragma unroll
    for (int it = 0; it < 2; it++) {
      int gi = tid*2 + it;
      int row = gi >> 2, g = gi & 3;
      uint32_t off = (uint32_t)((row >> 3)*512 + g*128 + (row & 7)*16);
      asm volatile("cp.async.cg.shared.global [%0], [%1], 16;"
                   :: "r"(aS[0] + off), "l"(tp + row*32 + g*8) : "memory");
      asm volatile("cp.async.cg.shared.global [%0], [%1], 16;"
                   :: "r"(bS[0] + off), "l"(tq + row*32 + g*8) : "memory");
    }
    asm volatile("cp.async.commit_group;" ::: "memory");
    asm volatile("cp.async.wait_group 0;" ::: "memory");
    __syncthreads();
    #pragma unroll
    for (int np = 0; np < 2; np++) {
      float W[4][2][4];
      #pragma unroll
      for (int mi = 0; mi < 4; mi++)
        #pragma unroll
        for (int nl = 0; nl < 2; nl++)
          #pragma unroll
          for (int v = 0; v < 4; v++) W[mi][nl][v] = 0.f;
      #pragma unroll
      for (int ks = 0; ks < 2; ks++) {
        uint32_t aF[4][4], bF[2][2];
        #pragma unroll
        for (int mi = 0; mi < 4; mi++)
          LDMX4(aF[mi][0], aF[mi][1], aF[mi][2], aF[mi][3], aS[0] + offA[ks][mi]);
        LDMX4(bF[0][0], bF[0][1], bF[1][0], bF[1][1], bS[0] + offB[ks][np]);
        #pragma unroll
        for (int mi = 0; mi < 4; mi++)
          #pragma unroll
          for (int nl = 0; nl < 2; nl++)
            MMA_F16(W[mi][nl], aF[mi], bF[nl]);
      }
      #pragma unroll
      for (int nl = 0; nl < 2; nl++) {
        int ni = np*2 + nl;
        #pragma unroll
        for (int mi = 0; mi < 4; mi++)
          #pragma unroll
          for (int h = 0; h < 2; h++) {
            int pi = mi*2 + h;
            unsigned long long sqp2 = pk2(sqp[pi], sqp[pi]);
            unsigned long long ss2 = add2_(sqp2, sqq2[ni]);
            PAIRK(W[mi][nl][2*h], W[mi][nl][2*h+1],
                  acc[mi*4+ni][2*h], acc[mi*4+ni][2*h+1], ss2);
          }
      }
    }
  }

  // per-tile end factor (diag identity: full-tile sum == f-weighted tri sum)
  float ef = diag ? 1.f : 2.f;
  if (type == 1) ef = -2.f;
  if (type == 2) ef *= TVSC_INV2;

  uint32_t llo_, lhi_;
  asm("mov.b64 {%0, %1}, %2;" : "=r"(llo_), "=r"(lhi_) : "l"(loc2));
  float local = __uint_as_float(llo_) + __uint_as_float(lhi_);
  #pragma unroll
  for (int o = 16; o > 0; o >>= 1) local += __shfl_down_sync(0xffffffffu, local, o);
  if (lane == 0) u.ep.red[warp] = local;
  __syncthreads();
  if (tid == 0) {
    float s = 0.f;
    #pragma unroll
    for (int wq = 0; wq < 8; wq++) s += u.ep.red[wq];
    g_partials[t0] = s * ef;
    __threadfence();
    fin = (atomicAdd(&g_ctr2, 1) == NTILES - 1);
  }
  __syncthreads();
  if (!fin) return;
  // final reduction by last CTA
  if (tid == 0) g_ctr2 = 0;
  __threadfence();
  double s = 0.0;
  for (int i = tid; i < NTILES; i += 256) s += (double)g_partials[i];
  u.ep.sdred[tid] = s; __syncthreads();
  for (int o = 128; o > 0; o >>= 1) {
    if (tid < o) u.ep.sdred[tid] += u.ep.sdred[tid + o];
    __syncthreads();
  }
  if (tid == 0) out[0] = (float)(u.ep.sdred[0] * (double)g_scalars[1]);
}

// ---------------------------------------------------------------------------
extern "C" void kernel_launch(void* const* d_in, const int* in_sizes, int n_in,
                              void* d_out, int out_size) {
  const float* src  = (const float*)d_in[0];
  const float* tgt  = (const float*)d_in[1];
  const void*  slab = d_in[2];
  const float* tlab = (const float*)d_in[3];

  k_pre     <<<2065, 256>>>(src, tgt, slab, tlab);   // launch 0
  k_fillnorm<<<384, 256>>>(src, tgt, slab, tlab);    // launch 1
  k_main    <<<NTILES, 256>>>((float*)d_out);        // launch 2
}